// round 2
// baseline (speedup 1.0000x reference)
#include <cuda_runtime.h>
#include <math.h>

// Problem dims (fixed by the dataset)
#define CDIM  768
#define TDIM  1024
#define BDIM  8
#define MROWS (BDIM * TDIM)   // 8192
#define FDIM  3072
#define NHEAD 12
#define HSIZE 64

// ---------------------------------------------------------------------------
// Scratch (no cudaMalloc allowed)
// ---------------------------------------------------------------------------
__device__ float g_h  [MROWS * CDIM];   // LN1 output
__device__ float g_q  [MROWS * CDIM];
__device__ float g_k  [MROWS * CDIM];
__device__ float g_v  [MROWS * CDIM];
__device__ float g_att[MROWS * CDIM];   // attention output (B,T,H,hs)
__device__ float g_x2 [MROWS * CDIM];   // x + attn@Wo + bo
__device__ float g_h2 [MROWS * CDIM];   // LN2 output
__device__ float g_ff [MROWS * FDIM];   // gelu(h2@W1+b1)

// ---------------------------------------------------------------------------
// LayerNorm: one block per row, 192 threads, one float4 per thread
// ---------------------------------------------------------------------------
__global__ void ln_kernel(const float* __restrict__ x,
                          const float* __restrict__ g,
                          const float* __restrict__ b,
                          float* __restrict__ out)
{
    const int row = blockIdx.x;
    const int t   = threadIdx.x;              // 0..191
    const float4 v = ((const float4*)(x + (size_t)row * CDIM))[t];

    float s = v.x + v.y + v.z + v.w;
    float q = v.x * v.x + v.y * v.y + v.z * v.z + v.w * v.w;

    __shared__ float ss[6], sq[6];
    #pragma unroll
    for (int off = 16; off > 0; off >>= 1) {
        s += __shfl_xor_sync(0xffffffffu, s, off);
        q += __shfl_xor_sync(0xffffffffu, q, off);
    }
    if ((t & 31) == 0) { ss[t >> 5] = s; sq[t >> 5] = q; }
    __syncthreads();
    s = ss[0] + ss[1] + ss[2] + ss[3] + ss[4] + ss[5];
    q = sq[0] + sq[1] + sq[2] + sq[3] + sq[4] + sq[5];

    const float mean = s * (1.0f / CDIM);
    const float var  = q * (1.0f / CDIM) - mean * mean;
    const float rstd = rsqrtf(var + 1e-5f);

    const float4 gv = ((const float4*)g)[t];
    const float4 bv = ((const float4*)b)[t];
    float4 o;
    o.x = (v.x - mean) * rstd * gv.x + bv.x;
    o.y = (v.y - mean) * rstd * gv.y + bv.y;
    o.z = (v.z - mean) * rstd * gv.z + bv.z;
    o.w = (v.w - mean) * rstd * gv.w + bv.w;
    ((float4*)(out + (size_t)row * CDIM))[t] = o;
}

// ---------------------------------------------------------------------------
// SGEMM: C[M,N] = A[M,K] @ B[K,N]  (row-major), 128x128x8 tiles, 8x8/thread.
// M,N,K all multiples of 128/8 here, so no bounds checks.
// ---------------------------------------------------------------------------
enum { EPI_NONE = 0, EPI_BIAS_RES = 1, EPI_BIAS_GELU = 2 };

__device__ __forceinline__ float gelu_exact(float x)
{
    return 0.5f * x * (1.0f + erff(x * 0.7071067811865475f));
}

template <int EPI>
__global__ void __launch_bounds__(256)
sgemm(int M, int N, int K,
      const float* __restrict__ A, const float* __restrict__ B,
      const float* __restrict__ bias, const float* __restrict__ res,
      float* __restrict__ Cmat)
{
    __shared__ float As[8][128];
    __shared__ float Bs[8][128];

    const int tid = threadIdx.x;
    const int tx  = tid & 15;       // 0..15 -> 8 output cols each
    const int ty  = tid >> 4;       // 0..15 -> 8 output rows each
    const int brow = blockIdx.y * 128;
    const int bcol = blockIdx.x * 128;

    float acc[8][8];
    #pragma unroll
    for (int i = 0; i < 8; i++)
        #pragma unroll
        for (int j = 0; j < 8; j++) acc[i][j] = 0.0f;

    const int arow = tid >> 1;          // 0..127
    const int acol = (tid & 1) << 2;    // 0 or 4
    const int bkr  = tid >> 5;          // 0..7
    const int bcl  = (tid & 31) << 2;   // 0..124

    const float* Ap = A + (size_t)(brow + arow) * K + acol;
    const float* Bp = B + (size_t)bkr * N + bcol + bcl;

    for (int k0 = 0; k0 < K; k0 += 8) {
        const float4 a4 = *(const float4*)(Ap + k0);
        const float4 b4 = *(const float4*)(Bp + (size_t)k0 * N);
        As[acol + 0][arow] = a4.x;
        As[acol + 1][arow] = a4.y;
        As[acol + 2][arow] = a4.z;
        As[acol + 3][arow] = a4.w;
        *(float4*)&Bs[bkr][bcl] = b4;
        __syncthreads();

        #pragma unroll
        for (int k = 0; k < 8; k++) {
            const float4 a0 = *(const float4*)&As[k][ty * 8];
            const float4 a1 = *(const float4*)&As[k][ty * 8 + 4];
            const float4 b0 = *(const float4*)&Bs[k][tx * 8];
            const float4 b1 = *(const float4*)&Bs[k][tx * 8 + 4];
            const float af[8] = {a0.x, a0.y, a0.z, a0.w, a1.x, a1.y, a1.z, a1.w};
            const float bf[8] = {b0.x, b0.y, b0.z, b0.w, b1.x, b1.y, b1.z, b1.w};
            #pragma unroll
            for (int i = 0; i < 8; i++)
                #pragma unroll
                for (int j = 0; j < 8; j++)
                    acc[i][j] = fmaf(af[i], bf[j], acc[i][j]);
        }
        __syncthreads();
    }

    #pragma unroll
    for (int i = 0; i < 8; i++) {
        const int r = brow + ty * 8 + i;
        float* crow = Cmat + (size_t)r * N + bcol;
        #pragma unroll
        for (int jj = 0; jj < 8; jj += 4) {
            const int c = tx * 8 + jj;
            float4 o = make_float4(acc[i][jj], acc[i][jj + 1],
                                   acc[i][jj + 2], acc[i][jj + 3]);
            if (EPI != EPI_NONE) {
                o.x += bias[bcol + c + 0];
                o.y += bias[bcol + c + 1];
                o.z += bias[bcol + c + 2];
                o.w += bias[bcol + c + 3];
            }
            if (EPI == EPI_BIAS_GELU) {
                o.x = gelu_exact(o.x); o.y = gelu_exact(o.y);
                o.z = gelu_exact(o.z); o.w = gelu_exact(o.w);
            }
            if (EPI == EPI_BIAS_RES) {
                const float4 rv = *(const float4*)(res + (size_t)r * N + bcol + c);
                o.x += rv.x; o.y += rv.y; o.z += rv.z; o.w += rv.w;
            }
            *(float4*)(crow + c) = o;
        }
    }
}

// ---------------------------------------------------------------------------
// Flash-style causal attention, fp32. One block per (q-tile of 64, b*h).
// 256 threads = 16x16; 4x4 micro-tiles. K stored transposed in smem for
// conflict-free S reads; K buffer is reused to hold P.
// ---------------------------------------------------------------------------
__global__ void __launch_bounds__(256)
attn_kernel(const float* __restrict__ Q, const float* __restrict__ K,
            const float* __restrict__ V, float* __restrict__ O)
{
    __shared__ float Qs [64][64];   // Qs[r][d]
    __shared__ float KPs[64][64];   // first Kt[d][c], later P[r][c]
    __shared__ float Vs [64][64];   // Vs[c][d]

    const int qt = blockIdx.x;              // 0..15
    const int bh = blockIdx.y;              // 0..95
    const int b  = bh / NHEAD;
    const int h  = bh % NHEAD;
    const size_t base = (size_t)b * TDIM * CDIM + (size_t)h * HSIZE;

    const int tid = threadIdx.x;
    const int tx  = tid & 15;   // 4 cols each
    const int ty  = tid >> 4;   // 4 rows each

    // load Q tile
    for (int idx = tid; idx < 64 * 16; idx += 256) {
        const int r = idx >> 4, d4 = (idx & 15) << 2;
        *(float4*)&Qs[r][d4] =
            *(const float4*)(Q + base + (size_t)(qt * 64 + r) * CDIM + d4);
    }

    float m[4], l[4], acc[4][4];
    #pragma unroll
    for (int i = 0; i < 4; i++) {
        m[i] = -INFINITY; l[i] = 0.0f;
        #pragma unroll
        for (int j = 0; j < 4; j++) acc[i][j] = 0.0f;
    }
    const float scale = 0.03608439182435161f;   // 768^-0.5 (NOTE: C, not hs)

    for (int jt = 0; jt <= qt; jt++) {
        __syncthreads();   // KPs/Vs reuse safe; also covers initial Q load
        for (int idx = tid; idx < 64 * 16; idx += 256) {
            const int r = idx >> 4, d4 = (idx & 15) << 2;
            const float4 kv =
                *(const float4*)(K + base + (size_t)(jt * 64 + r) * CDIM + d4);
            KPs[d4 + 0][r] = kv.x; KPs[d4 + 1][r] = kv.y;
            KPs[d4 + 2][r] = kv.z; KPs[d4 + 3][r] = kv.w;
            *(float4*)&Vs[r][d4] =
                *(const float4*)(V + base + (size_t)(jt * 64 + r) * CDIM + d4);
        }
        __syncthreads();

        // S = Q K^T  (4x4 per thread)
        float s[4][4];
        #pragma unroll
        for (int i = 0; i < 4; i++)
            #pragma unroll
            for (int j = 0; j < 4; j++) s[i][j] = 0.0f;
        #pragma unroll 4
        for (int d = 0; d < 64; d++) {
            float qf[4], kf[4];
            #pragma unroll
            for (int i = 0; i < 4; i++) qf[i] = Qs[ty * 4 + i][d];
            #pragma unroll
            for (int j = 0; j < 4; j++) kf[j] = KPs[d][tx * 4 + j];
            #pragma unroll
            for (int i = 0; i < 4; i++)
                #pragma unroll
                for (int j = 0; j < 4; j++)
                    s[i][j] = fmaf(qf[i], kf[j], s[i][j]);
        }

        // scale + causal mask
        #pragma unroll
        for (int i = 0; i < 4; i++) {
            const int r = qt * 64 + ty * 4 + i;
            #pragma unroll
            for (int j = 0; j < 4; j++) {
                const int c = jt * 64 + tx * 4 + j;
                s[i][j] = (c <= r) ? s[i][j] * scale : -1e30f;
            }
        }

        // online softmax stats (reduce across the 16 tx lanes of this row group)
        #pragma unroll
        for (int i = 0; i < 4; i++) {
            float mx = fmaxf(fmaxf(s[i][0], s[i][1]), fmaxf(s[i][2], s[i][3]));
            #pragma unroll
            for (int off = 8; off > 0; off >>= 1)
                mx = fmaxf(mx, __shfl_xor_sync(0xffffffffu, mx, off, 16));
            const float mn    = fmaxf(m[i], mx);
            const float alpha = __expf(m[i] - mn);
            m[i] = mn;
            float rs = 0.0f;
            #pragma unroll
            for (int j = 0; j < 4; j++) {
                s[i][j] = __expf(s[i][j] - mn);
                rs += s[i][j];
            }
            #pragma unroll
            for (int off = 8; off > 0; off >>= 1)
                rs += __shfl_xor_sync(0xffffffffu, rs, off, 16);
            l[i] = l[i] * alpha + rs;
            #pragma unroll
            for (int j = 0; j < 4; j++) acc[i][j] *= alpha;
        }

        __syncthreads();   // everyone done reading K from KPs
        #pragma unroll
        for (int i = 0; i < 4; i++)
            #pragma unroll
            for (int j = 0; j < 4; j++)
                KPs[ty * 4 + i][tx * 4 + j] = s[i][j];   // P[r][c]
        __syncthreads();

        // O += P V
        #pragma unroll 4
        for (int c = 0; c < 64; c++) {
            float pf[4], vf[4];
            #pragma unroll
            for (int i = 0; i < 4; i++) pf[i] = KPs[ty * 4 + i][c];
            #pragma unroll
            for (int j = 0; j < 4; j++) vf[j] = Vs[c][tx * 4 + j];
            #pragma unroll
            for (int i = 0; i < 4; i++)
                #pragma unroll
                for (int j = 0; j < 4; j++)
                    acc[i][j] = fmaf(pf[i], vf[j], acc[i][j]);
        }
    }

    #pragma unroll
    for (int i = 0; i < 4; i++) {
        const float inv = 1.0f / l[i];
        const float4 o = make_float4(acc[i][0] * inv, acc[i][1] * inv,
                                     acc[i][2] * inv, acc[i][3] * inv);
        *(float4*)(O + base + (size_t)(qt * 64 + ty * 4 + i) * CDIM + tx * 4) = o;
    }
}

// ---------------------------------------------------------------------------
// Launch
// ---------------------------------------------------------------------------
extern "C" void kernel_launch(void* const* d_in, const int* in_sizes, int n_in,
                              void* d_out, int out_size)
{
    const float* x   = (const float*)d_in[0];
    const float* Wq  = (const float*)d_in[1];
    const float* Wk  = (const float*)d_in[2];
    const float* Wv  = (const float*)d_in[3];
    const float* Wo  = (const float*)d_in[4];
    const float* bo  = (const float*)d_in[5];
    const float* W1  = (const float*)d_in[6];
    const float* b1  = (const float*)d_in[7];
    const float* W2  = (const float*)d_in[8];
    const float* b2  = (const float*)d_in[9];
    const float* g1  = (const float*)d_in[10];
    const float* be1 = (const float*)d_in[11];
    const float* g2  = (const float*)d_in[12];
    const float* be2 = (const float*)d_in[13];
    float* out = (float*)d_out;

    float *h, *q, *k, *v, *att, *x2, *h2, *ff;
    cudaGetSymbolAddress((void**)&h,   g_h);
    cudaGetSymbolAddress((void**)&q,   g_q);
    cudaGetSymbolAddress((void**)&k,   g_k);
    cudaGetSymbolAddress((void**)&v,   g_v);
    cudaGetSymbolAddress((void**)&att, g_att);
    cudaGetSymbolAddress((void**)&x2,  g_x2);
    cudaGetSymbolAddress((void**)&h2,  g_h2);
    cudaGetSymbolAddress((void**)&ff,  g_ff);

    const dim3 blk(256);
    const dim3 g768(CDIM / 128, MROWS / 128);    // (6, 64)
    const dim3 g3072(FDIM / 128, MROWS / 128);   // (24, 64)

    // 1) h = LN(x)
    ln_kernel<<<MROWS, 192>>>(x, g1, be1, h);

    // 2) q/k/v = h @ W{q,k,v}
    sgemm<EPI_NONE><<<g768, blk>>>(MROWS, CDIM, CDIM, h, Wq, nullptr, nullptr, q);
    sgemm<EPI_NONE><<<g768, blk>>>(MROWS, CDIM, CDIM, h, Wk, nullptr, nullptr, k);
    sgemm<EPI_NONE><<<g768, blk>>>(MROWS, CDIM, CDIM, h, Wv, nullptr, nullptr, v);

    // 3) causal attention
    attn_kernel<<<dim3(TDIM / 64, BDIM * NHEAD), blk>>>(q, k, v, att);

    // 4) x2 = x + att @ Wo + bo
    sgemm<EPI_BIAS_RES><<<g768, blk>>>(MROWS, CDIM, CDIM, att, Wo, bo, x, x2);

    // 5) h2 = LN(x2)
    ln_kernel<<<MROWS, 192>>>(x2, g2, be2, h2);

    // 6) ff = gelu(h2 @ W1 + b1)
    sgemm<EPI_BIAS_GELU><<<g3072, blk>>>(MROWS, FDIM, CDIM, h2, W1, b1, nullptr, ff);

    // 7) out = x2 + ff @ W2 + b2
    sgemm<EPI_BIAS_RES><<<g768, blk>>>(MROWS, CDIM, FDIM, ff, W2, b2, x2, out);
}

// round 5
// speedup vs baseline: 4.0995x; 4.0995x over previous
#include <cuda_runtime.h>
#include <cuda_fp16.h>
#include <math.h>
#include <stdint.h>

#define CDIM  768
#define TDIM  1024
#define BDIM  8
#define MROWS 8192
#define FDIM  3072
#define NHEAD 12
#define HSIZE 64

// ===========================================================================
// Scratch (no cudaMalloc allowed)
// ===========================================================================
__device__ __half g_h  [MROWS * CDIM];   // LN1 out, fp16
__device__ __half g_att[MROWS * CDIM];   // attention out, fp16
__device__ __half g_h2 [MROWS * CDIM];   // LN2 out, fp16
__device__ __half g_ff [MROWS * FDIM];   // gelu(h2@W1+b1), fp16
__device__ float  g_q  [MROWS * CDIM], g_k[MROWS * CDIM], g_v[MROWS * CDIM];
__device__ float  g_x2 [MROWS * CDIM];
// transposed weights, [N,K] K-major fp16
__device__ __half g_Wq[CDIM * CDIM], g_Wk[CDIM * CDIM], g_Wv[CDIM * CDIM];
__device__ __half g_Wo[CDIM * CDIM];
__device__ __half g_W1[CDIM * FDIM];     // [N=3072, K=768]
__device__ __half g_W2[FDIM * CDIM];     // [N=768,  K=3072]

__device__ __forceinline__ uint32_t smem_u32(const void* p) {
    uint32_t a;
    asm("{ .reg .u64 t; cvta.to.shared.u64 t, %1; cvt.u32.u64 %0, t; }"
        : "=r"(a) : "l"(p));
    return a;
}
#define SWZ(off) ((off) ^ (((off) >> 3) & 0x70))

// ===========================================================================
// Weight transpose:  W[K,N] fp32 -> Wt[N,K] fp16
// ===========================================================================
__global__ void wtrans(const float* __restrict__ W, __half* __restrict__ Wt,
                       int K, int N)
{
    __shared__ float t[32][33];
    const int n0 = blockIdx.x * 32, k0 = blockIdx.y * 32;
    const int tx = threadIdx.x, ty = threadIdx.y;   // 32 x 8
    #pragma unroll
    for (int r = 0; r < 32; r += 8)
        t[ty + r][tx] = W[(size_t)(k0 + ty + r) * N + n0 + tx];
    __syncthreads();
    #pragma unroll
    for (int r = 0; r < 32; r += 8)
        Wt[(size_t)(n0 + ty + r) * K + k0 + tx] = __float2half_rn(t[tx][ty + r]);
}

// ===========================================================================
// LayerNorm -> fp16 (one block per row, 192 threads)
// ===========================================================================
__global__ void ln_half(const float* __restrict__ x, const float* __restrict__ g,
                        const float* __restrict__ b, __half* __restrict__ out)
{
    const int row = blockIdx.x;
    const int t   = threadIdx.x;
    const float4 v = ((const float4*)(x + (size_t)row * CDIM))[t];

    float s = v.x + v.y + v.z + v.w;
    float q = v.x * v.x + v.y * v.y + v.z * v.z + v.w * v.w;
    __shared__ float ss[6], sq[6];
    #pragma unroll
    for (int off = 16; off > 0; off >>= 1) {
        s += __shfl_xor_sync(0xffffffffu, s, off);
        q += __shfl_xor_sync(0xffffffffu, q, off);
    }
    if ((t & 31) == 0) { ss[t >> 5] = s; sq[t >> 5] = q; }
    __syncthreads();
    s = ss[0] + ss[1] + ss[2] + ss[3] + ss[4] + ss[5];
    q = sq[0] + sq[1] + sq[2] + sq[3] + sq[4] + sq[5];

    const float mean = s * (1.0f / CDIM);
    const float var  = q * (1.0f / CDIM) - mean * mean;
    const float rstd = rsqrtf(var + 1e-5f);

    const float4 gv = ((const float4*)g)[t];
    const float4 bv = ((const float4*)b)[t];
    __half2 o01 = __floats2half2_rn((v.x - mean) * rstd * gv.x + bv.x,
                                    (v.y - mean) * rstd * gv.y + bv.y);
    __half2 o23 = __floats2half2_rn((v.z - mean) * rstd * gv.z + bv.z,
                                    (v.w - mean) * rstd * gv.w + bv.w);
    ((__half2*)(out + (size_t)row * CDIM))[t * 2]     = o01;
    ((__half2*)(out + (size_t)row * CDIM))[t * 2 + 1] = o23;
}

// ===========================================================================
// fp16 mma.sync GEMM:  C[M,N] = A[M,K] @ B[N,K]^T
// 128x128x64 tiles, double-buffered cp.async, 8 warps (4x2), warp tile 32x64.
// ===========================================================================
enum { EPI_F32 = 0, EPI_BIAS_RES = 1, EPI_BIAS_GELU_H = 2 };

#define BM 128
#define BN 128
#define BK 64
#define ATILE (BM * BK * 2)               // 16384 B
#define STAGE (ATILE * 2)                 // A + B = 32768 B
#define GEMM_SMEM (2 * STAGE)             // 65536 B

__device__ __forceinline__ float gelu_exact(float x) {
    return 0.5f * x * (1.0f + erff(x * 0.7071067811865475f));
}

__device__ __forceinline__ void ldsm4(uint32_t* r, uint32_t addr) {
    asm volatile("ldmatrix.sync.aligned.m8n8.x4.shared.b16 {%0,%1,%2,%3}, [%4];"
                 : "=r"(r[0]), "=r"(r[1]), "=r"(r[2]), "=r"(r[3]) : "r"(addr));
}
__device__ __forceinline__ void mma16816(float* d, const uint32_t* a,
                                         uint32_t b0, uint32_t b1) {
    asm volatile("mma.sync.aligned.m16n8k16.row.col.f32.f16.f16.f32 "
                 "{%0,%1,%2,%3}, {%4,%5,%6,%7}, {%8,%9}, {%0,%1,%2,%3};"
                 : "+f"(d[0]), "+f"(d[1]), "+f"(d[2]), "+f"(d[3])
                 : "r"(a[0]), "r"(a[1]), "r"(a[2]), "r"(a[3]), "r"(b0), "r"(b1));
}

template <int EPI>
__global__ void __launch_bounds__(256)
gemm_mma(int M, int N, int K,
         const __half* __restrict__ A, const __half* __restrict__ B,
         const float* __restrict__ bias, const float* __restrict__ res,
         float* __restrict__ Cf, __half* __restrict__ Ch)
{
    extern __shared__ char smem[];
    const uint32_t sbase = smem_u32(smem);
    const int tid  = threadIdx.x;
    const int lane = tid & 31;
    const int wid  = tid >> 5;
    const int wm   = wid >> 1;          // 0..3 -> 32-row band
    const int wn   = wid & 1;           // 0..1 -> 64-col band
    const int brow = blockIdx.y * BM, bcol = blockIdx.x * BN;

    float acc[2][8][4];
    #pragma unroll
    for (int i = 0; i < 2; i++)
        #pragma unroll
        for (int j = 0; j < 8; j++)
            #pragma unroll
            for (int c = 0; c < 4; c++) acc[i][j][c] = 0.0f;

    const int nst = K / BK;

    // per-thread cp.async coords: 4 chunks of 16B per tile
    const int lr0 = tid >> 3;           // rows tid/8, +32, +64, +96
    const int lc  = (tid & 7) * 16;     // byte col within 128B row

    auto issue_stage = [&](int s) {
        const int buf = s & 1;
        const int k0  = s * BK;
        const uint32_t sA = sbase + buf * STAGE;
        const uint32_t sB = sA + ATILE;
        #pragma unroll
        for (int c = 0; c < 4; c++) {
            const int row = lr0 + c * 32;
            const uint32_t so = SWZ((uint32_t)(row * 128 + lc));
            const __half* gA = A + (size_t)(brow + row) * K + k0 + (lc >> 1);
            const __half* gB = B + (size_t)(bcol + row) * K + k0 + (lc >> 1);
            asm volatile("cp.async.cg.shared.global [%0], [%1], 16;"
                         :: "r"(sA + so), "l"(gA));
            asm volatile("cp.async.cg.shared.global [%0], [%1], 16;"
                         :: "r"(sB + so), "l"(gB));
        }
        asm volatile("cp.async.commit_group;" ::: "memory");
    };

    issue_stage(0);
    issue_stage(1);

    // ldmatrix lane addressing (constant per thread)
    const int a_row = wm * 32 + (lane & 15);            // + mi*16
    const int a_kb  = (lane >> 4) << 4;                 // 0 / 16
    const int b_row = wn * 64 + ((lane >> 4) << 3) + (lane & 7);  // + bj*16
    const int b_kb  = ((lane >> 3) & 1) << 4;           // 0 / 16

    for (int s = 0; s < nst; s++) {
        if (s < nst - 1) asm volatile("cp.async.wait_group 1;" ::: "memory");
        else             asm volatile("cp.async.wait_group 0;" ::: "memory");
        __syncthreads();

        const uint32_t sA = sbase + (s & 1) * STAGE;
        const uint32_t sB = sA + ATILE;

        #pragma unroll
        for (int kk = 0; kk < 4; kk++) {
            uint32_t af[2][4], bf[4][4];
            #pragma unroll
            for (int mi = 0; mi < 2; mi++)
                ldsm4(af[mi], sA + SWZ((uint32_t)((a_row + mi * 16) * 128 +
                                                  a_kb + kk * 32)));
            #pragma unroll
            for (int bj = 0; bj < 4; bj++)
                ldsm4(bf[bj], sB + SWZ((uint32_t)((b_row + bj * 16) * 128 +
                                                  b_kb + kk * 32)));
            #pragma unroll
            for (int mi = 0; mi < 2; mi++)
                #pragma unroll
                for (int ni = 0; ni < 8; ni++)
                    mma16816(acc[mi][ni], af[mi],
                             bf[ni >> 1][(ni & 1) * 2],
                             bf[ni >> 1][(ni & 1) * 2 + 1]);
        }
        __syncthreads();
        if (s + 2 < nst) issue_stage(s + 2);
    }

    // epilogue: thread holds (row = brow + wm*32 + mi*16 + lane/4 (+8),
    //                         col = bcol + wn*64 + ni*8 + (lane%4)*2)
    const int er = brow + wm * 32 + (lane >> 2);
    const int ec = bcol + wn * 64 + (lane & 3) * 2;
    #pragma unroll
    for (int mi = 0; mi < 2; mi++) {
        #pragma unroll
        for (int half = 0; half < 2; half++) {
            const int r = er + mi * 16 + half * 8;
            #pragma unroll
            for (int ni = 0; ni < 8; ni++) {
                const int c = ec + ni * 8;
                const float d0 = acc[mi][ni][half * 2];
                const float d1 = acc[mi][ni][half * 2 + 1];
                if (EPI == EPI_F32) {
                    *(float2*)(Cf + (size_t)r * N + c) = make_float2(d0, d1);
                } else if (EPI == EPI_BIAS_RES) {
                    const float2 rv = *(const float2*)(res + (size_t)r * N + c);
                    *(float2*)(Cf + (size_t)r * N + c) =
                        make_float2(d0 + bias[c] + rv.x, d1 + bias[c + 1] + rv.y);
                } else {
                    const float a = gelu_exact(d0 + bias[c]);
                    const float b = gelu_exact(d1 + bias[c + 1]);
                    *(__half2*)(Ch + (size_t)r * N + c) = __floats2half2_rn(a, b);
                }
            }
        }
    }
}

// ===========================================================================
// Flash-style causal attention: fp32 compute, fp16 out.
// ===========================================================================
__global__ void __launch_bounds__(256)
attn_kernel(const float* __restrict__ Q, const float* __restrict__ K,
            const float* __restrict__ V, __half* __restrict__ O)
{
    __shared__ float Qs [64][64];
    __shared__ float KPs[64][64];
    __shared__ float Vs [64][64];

    const int qt = blockIdx.x;
    const int bh = blockIdx.y;
    const int b  = bh / NHEAD;
    const int h  = bh % NHEAD;
    const size_t base = (size_t)b * TDIM * CDIM + (size_t)h * HSIZE;

    const int tid = threadIdx.x;
    const int tx  = tid & 15;
    const int ty  = tid >> 4;

    for (int idx = tid; idx < 64 * 16; idx += 256) {
        const int r = idx >> 4, d4 = (idx & 15) << 2;
        *(float4*)&Qs[r][d4] =
            *(const float4*)(Q + base + (size_t)(qt * 64 + r) * CDIM + d4);
    }

    float m[4], l[4], acc[4][4];
    #pragma unroll
    for (int i = 0; i < 4; i++) {
        m[i] = -INFINITY; l[i] = 0.0f;
        #pragma unroll
        for (int j = 0; j < 4; j++) acc[i][j] = 0.0f;
    }
    const float scale = 0.03608439182435161f;   // 768^-0.5 (C, not hs)

    for (int jt = 0; jt <= qt; jt++) {
        __syncthreads();
        for (int idx = tid; idx < 64 * 16; idx += 256) {
            const int r = idx >> 4, d4 = (idx & 15) << 2;
            const float4 kv =
                *(const float4*)(K + base + (size_t)(jt * 64 + r) * CDIM + d4);
            KPs[d4 + 0][r] = kv.x; KPs[d4 + 1][r] = kv.y;
            KPs[d4 + 2][r] = kv.z; KPs[d4 + 3][r] = kv.w;
            *(float4*)&Vs[r][d4] =
                *(const float4*)(V + base + (size_t)(jt * 64 + r) * CDIM + d4);
        }
        __syncthreads();

        float s[4][4];
        #pragma unroll
        for (int i = 0; i < 4; i++)
            #pragma unroll
            for (int j = 0; j < 4; j++) s[i][j] = 0.0f;
        #pragma unroll 4
        for (int d = 0; d < 64; d++) {
            float qf[4], kf[4];
            #pragma unroll
            for (int i = 0; i < 4; i++) qf[i] = Qs[ty * 4 + i][d];
            #pragma unroll
            for (int j = 0; j < 4; j++) kf[j] = KPs[d][tx * 4 + j];
            #pragma unroll
            for (int i = 0; i < 4; i++)
                #pragma unroll
                for (int j = 0; j < 4; j++)
                    s[i][j] = fmaf(qf[i], kf[j], s[i][j]);
        }

        #pragma unroll
        for (int i = 0; i < 4; i++) {
            const int r = qt * 64 + ty * 4 + i;
            #pragma unroll
            for (int j = 0; j < 4; j++) {
                const int c = jt * 64 + tx * 4 + j;
                s[i][j] = (c <= r) ? s[i][j] * scale : -1e30f;
            }
        }

        #pragma unroll
        for (int i = 0; i < 4; i++) {
            float mx = fmaxf(fmaxf(s[i][0], s[i][1]), fmaxf(s[i][2], s[i][3]));
            #pragma unroll
            for (int off = 8; off > 0; off >>= 1)
                mx = fmaxf(mx, __shfl_xor_sync(0xffffffffu, mx, off, 16));
            const float mn    = fmaxf(m[i], mx);
            const float alpha = __expf(m[i] - mn);
            m[i] = mn;
            float rs = 0.0f;
            #pragma unroll
            for (int j = 0; j < 4; j++) {
                s[i][j] = __expf(s[i][j] - mn);
                rs += s[i][j];
            }
            #pragma unroll
            for (int off = 8; off > 0; off >>= 1)
                rs += __shfl_xor_sync(0xffffffffu, rs, off, 16);
            l[i] = l[i] * alpha + rs;
            #pragma unroll
            for (int j = 0; j < 4; j++) acc[i][j] *= alpha;
        }

        __syncthreads();
        #pragma unroll
        for (int i = 0; i < 4; i++)
            #pragma unroll
            for (int j = 0; j < 4; j++)
                KPs[ty * 4 + i][tx * 4 + j] = s[i][j];
        __syncthreads();

        #pragma unroll 4
        for (int c = 0; c < 64; c++) {
            float pf[4], vf[4];
            #pragma unroll
            for (int i = 0; i < 4; i++) pf[i] = KPs[ty * 4 + i][c];
            #pragma unroll
            for (int j = 0; j < 4; j++) vf[j] = Vs[c][tx * 4 + j];
            #pragma unroll
            for (int i = 0; i < 4; i++)
                #pragma unroll
                for (int j = 0; j < 4; j++)
                    acc[i][j] = fmaf(pf[i], vf[j], acc[i][j]);
        }
    }

    #pragma unroll
    for (int i = 0; i < 4; i++) {
        const float inv = 1.0f / l[i];
        const size_t off = base + (size_t)(qt * 64 + ty * 4 + i) * CDIM + tx * 4;
        *(__half2*)(O + off)     = __floats2half2_rn(acc[i][0] * inv, acc[i][1] * inv);
        *(__half2*)(O + off + 2) = __floats2half2_rn(acc[i][2] * inv, acc[i][3] * inv);
    }
}

// ===========================================================================
// Launch
// ===========================================================================
extern "C" void kernel_launch(void* const* d_in, const int* in_sizes, int n_in,
                              void* d_out, int out_size)
{
    const float* x   = (const float*)d_in[0];
    const float* Wq  = (const float*)d_in[1];
    const float* Wk  = (const float*)d_in[2];
    const float* Wv  = (const float*)d_in[3];
    const float* Wo  = (const float*)d_in[4];
    const float* bo  = (const float*)d_in[5];
    const float* W1  = (const float*)d_in[6];
    const float* b1  = (const float*)d_in[7];
    const float* W2  = (const float*)d_in[8];
    const float* b2  = (const float*)d_in[9];
    const float* g1  = (const float*)d_in[10];
    const float* be1 = (const float*)d_in[11];
    const float* g2  = (const float*)d_in[12];
    const float* be2 = (const float*)d_in[13];
    float* out = (float*)d_out;

    __half *h, *att, *h2, *ff, *wq, *wk, *wv, *wo, *w1, *w2;
    float *q, *k, *v, *x2;
    cudaGetSymbolAddress((void**)&h,  g_h);   cudaGetSymbolAddress((void**)&att, g_att);
    cudaGetSymbolAddress((void**)&h2, g_h2);  cudaGetSymbolAddress((void**)&ff,  g_ff);
    cudaGetSymbolAddress((void**)&wq, g_Wq);  cudaGetSymbolAddress((void**)&wk,  g_Wk);
    cudaGetSymbolAddress((void**)&wv, g_Wv);  cudaGetSymbolAddress((void**)&wo,  g_Wo);
    cudaGetSymbolAddress((void**)&w1, g_W1);  cudaGetSymbolAddress((void**)&w2,  g_W2);
    cudaGetSymbolAddress((void**)&q,  g_q);   cudaGetSymbolAddress((void**)&k,   g_k);
    cudaGetSymbolAddress((void**)&v,  g_v);   cudaGetSymbolAddress((void**)&x2,  g_x2);

    cudaFuncSetAttribute(gemm_mma<EPI_F32>,
                         cudaFuncAttributeMaxDynamicSharedMemorySize, GEMM_SMEM);
    cudaFuncSetAttribute(gemm_mma<EPI_BIAS_RES>,
                         cudaFuncAttributeMaxDynamicSharedMemorySize, GEMM_SMEM);
    cudaFuncSetAttribute(gemm_mma<EPI_BIAS_GELU_H>,
                         cudaFuncAttributeMaxDynamicSharedMemorySize, GEMM_SMEM);

    const dim3 wblk(32, 8);
    wtrans<<<dim3(CDIM / 32, CDIM / 32), wblk>>>(Wq, wq, CDIM, CDIM);
    wtrans<<<dim3(CDIM / 32, CDIM / 32), wblk>>>(Wk, wk, CDIM, CDIM);
    wtrans<<<dim3(CDIM / 32, CDIM / 32), wblk>>>(Wv, wv, CDIM, CDIM);
    wtrans<<<dim3(CDIM / 32, CDIM / 32), wblk>>>(Wo, wo, CDIM, CDIM);
    wtrans<<<dim3(FDIM / 32, CDIM / 32), wblk>>>(W1, w1, CDIM, FDIM);
    wtrans<<<dim3(CDIM / 32, FDIM / 32), wblk>>>(W2, w2, FDIM, CDIM);

    ln_half<<<MROWS, 192>>>(x, g1, be1, h);

    const dim3 g768(CDIM / 128, MROWS / 128);    // (6, 64)
    const dim3 g3072(FDIM / 128, MROWS / 128);   // (24, 64)

    gemm_mma<EPI_F32><<<g768, 256, GEMM_SMEM>>>(MROWS, CDIM, CDIM,
        h, wq, nullptr, nullptr, q, nullptr);
    gemm_mma<EPI_F32><<<g768, 256, GEMM_SMEM>>>(MROWS, CDIM, CDIM,
        h, wk, nullptr, nullptr, k, nullptr);
    gemm_mma<EPI_F32><<<g768, 256, GEMM_SMEM>>>(MROWS, CDIM, CDIM,
        h, wv, nullptr, nullptr, v, nullptr);

    attn_kernel<<<dim3(TDIM / 64, BDIM * NHEAD), 256>>>(q, k, v, att);

    gemm_mma<EPI_BIAS_RES><<<g768, 256, GEMM_SMEM>>>(MROWS, CDIM, CDIM,
        att, wo, bo, x, x2, nullptr);

    ln_half<<<MROWS, 192>>>(x2, g2, be2, h2);

    gemm_mma<EPI_BIAS_GELU_H><<<g3072, 256, GEMM_SMEM>>>(MROWS, FDIM, CDIM,
        h2, w1, b1, nullptr, nullptr, ff);

    gemm_mma<EPI_BIAS_RES><<<g768, 256, GEMM_SMEM>>>(MROWS, CDIM, FDIM,
        ff, w2, b2, x2, out, nullptr);
}

// round 6
// speedup vs baseline: 8.1776x; 1.9947x over previous
#include <cuda_runtime.h>
#include <cuda_fp16.h>
#include <math.h>
#include <stdint.h>

#define CDIM  768
#define TDIM  1024
#define BDIM  8
#define MROWS 8192
#define FDIM  3072
#define NHEAD 12
#define HSIZE 64
#define QKVW  2304

// ===========================================================================
// Scratch (no cudaMalloc allowed)
// ===========================================================================
__device__ __half g_h   [MROWS * CDIM];   // LN1 out, fp16
__device__ __half g_qkv [MROWS * QKVW];   // fused q|k|v, fp16
__device__ __half g_att [MROWS * CDIM];   // attention out, fp16
__device__ __half g_h2  [MROWS * CDIM];   // LN2 out, fp16
__device__ __half g_ff  [MROWS * FDIM];   // gelu(h2@W1+b1), fp16
__device__ float  g_x2  [MROWS * CDIM];
// transposed weights, [N,K] K-major fp16
__device__ __half g_Wqkv[QKVW * CDIM];    // rows: 0..767 Wq, 768.. Wk, 1536.. Wv
__device__ __half g_Wo  [CDIM * CDIM];
__device__ __half g_W1  [CDIM * FDIM];    // [N=3072, K=768]
__device__ __half g_W2  [FDIM * CDIM];    // [N=768,  K=3072]

__device__ __forceinline__ uint32_t smem_u32(const void* p) {
    uint32_t a;
    asm("{ .reg .u64 t; cvta.to.shared.u64 t, %1; cvt.u32.u64 %0, t; }"
        : "=r"(a) : "l"(p));
    return a;
}
#define SWZ(off) ((off) ^ (((off) >> 3) & 0x70))

__device__ __forceinline__ void ldsm4(uint32_t* r, uint32_t addr) {
    asm volatile("ldmatrix.sync.aligned.m8n8.x4.shared.b16 {%0,%1,%2,%3}, [%4];"
                 : "=r"(r[0]), "=r"(r[1]), "=r"(r[2]), "=r"(r[3]) : "r"(addr));
}
__device__ __forceinline__ void ldsm4t(uint32_t* r, uint32_t addr) {
    asm volatile("ldmatrix.sync.aligned.m8n8.x4.trans.shared.b16 {%0,%1,%2,%3}, [%4];"
                 : "=r"(r[0]), "=r"(r[1]), "=r"(r[2]), "=r"(r[3]) : "r"(addr));
}
__device__ __forceinline__ void mma16816(float* d, const uint32_t* a,
                                         uint32_t b0, uint32_t b1) {
    asm volatile("mma.sync.aligned.m16n8k16.row.col.f32.f16.f16.f32 "
                 "{%0,%1,%2,%3}, {%4,%5,%6,%7}, {%8,%9}, {%0,%1,%2,%3};"
                 : "+f"(d[0]), "+f"(d[1]), "+f"(d[2]), "+f"(d[3])
                 : "r"(a[0]), "r"(a[1]), "r"(a[2]), "r"(a[3]), "r"(b0), "r"(b1));
}
__device__ __forceinline__ uint32_t pack_h2(float a, float b) {
    __half2 h = __floats2half2_rn(a, b);
    return *(uint32_t*)&h;
}

// ===========================================================================
// Weight transpose:  W[K,N] fp32 -> Wt[N,K] fp16
// ===========================================================================
__global__ void wtrans(const float* __restrict__ W, __half* __restrict__ Wt,
                       int K, int N)
{
    __shared__ float t[32][33];
    const int n0 = blockIdx.x * 32, k0 = blockIdx.y * 32;
    const int tx = threadIdx.x, ty = threadIdx.y;   // 32 x 8
    #pragma unroll
    for (int r = 0; r < 32; r += 8)
        t[ty + r][tx] = W[(size_t)(k0 + ty + r) * N + n0 + tx];
    __syncthreads();
    #pragma unroll
    for (int r = 0; r < 32; r += 8)
        Wt[(size_t)(n0 + ty + r) * K + k0 + tx] = __float2half_rn(t[tx][ty + r]);
}

// ===========================================================================
// LayerNorm -> fp16 (one block per row, 192 threads)
// ===========================================================================
__global__ void ln_half(const float* __restrict__ x, const float* __restrict__ g,
                        const float* __restrict__ b, __half* __restrict__ out)
{
    const int row = blockIdx.x;
    const int t   = threadIdx.x;
    const float4 v = ((const float4*)(x + (size_t)row * CDIM))[t];

    float s = v.x + v.y + v.z + v.w;
    float q = v.x * v.x + v.y * v.y + v.z * v.z + v.w * v.w;
    __shared__ float ss[6], sq[6];
    #pragma unroll
    for (int off = 16; off > 0; off >>= 1) {
        s += __shfl_xor_sync(0xffffffffu, s, off);
        q += __shfl_xor_sync(0xffffffffu, q, off);
    }
    if ((t & 31) == 0) { ss[t >> 5] = s; sq[t >> 5] = q; }
    __syncthreads();
    s = ss[0] + ss[1] + ss[2] + ss[3] + ss[4] + ss[5];
    q = sq[0] + sq[1] + sq[2] + sq[3] + sq[4] + sq[5];

    const float mean = s * (1.0f / CDIM);
    const float var  = q * (1.0f / CDIM) - mean * mean;
    const float rstd = rsqrtf(var + 1e-5f);

    const float4 gv = ((const float4*)g)[t];
    const float4 bv = ((const float4*)b)[t];
    __half2 o01 = __floats2half2_rn((v.x - mean) * rstd * gv.x + bv.x,
                                    (v.y - mean) * rstd * gv.y + bv.y);
    __half2 o23 = __floats2half2_rn((v.z - mean) * rstd * gv.z + bv.z,
                                    (v.w - mean) * rstd * gv.w + bv.w);
    ((__half2*)(out + (size_t)row * CDIM))[t * 2]     = o01;
    ((__half2*)(out + (size_t)row * CDIM))[t * 2 + 1] = o23;
}

// ===========================================================================
// fp16 mma.sync GEMM:  C[M,N] = A[M,K] @ B[N,K]^T
// 128x128x64 tiles, double-buffered cp.async, 8 warps (4x2), warp tile 32x64.
// ===========================================================================
enum { EPI_HALF = 0, EPI_BIAS_RES = 1, EPI_BIAS_GELU_H = 2 };

#define BM 128
#define BN 128
#define BK 64
#define ATILE (BM * BK * 2)               // 16384 B
#define STAGE (ATILE * 2)                 // A + B = 32768 B
#define GEMM_SMEM (2 * STAGE)             // 65536 B

__device__ __forceinline__ float gelu_exact(float x) {
    return 0.5f * x * (1.0f + erff(x * 0.7071067811865475f));
}

template <int EPI>
__global__ void __launch_bounds__(256)
gemm_mma(int M, int N, int K,
         const __half* __restrict__ A, const __half* __restrict__ B,
         const float* __restrict__ bias, const float* __restrict__ res,
         float* __restrict__ Cf, __half* __restrict__ Ch)
{
    extern __shared__ char smem[];
    const uint32_t sbase = smem_u32(smem);
    const int tid  = threadIdx.x;
    const int lane = tid & 31;
    const int wid  = tid >> 5;
    const int wm   = wid >> 1;          // 0..3 -> 32-row band
    const int wn   = wid & 1;           // 0..1 -> 64-col band
    const int brow = blockIdx.y * BM, bcol = blockIdx.x * BN;

    float acc[2][8][4];
    #pragma unroll
    for (int i = 0; i < 2; i++)
        #pragma unroll
        for (int j = 0; j < 8; j++)
            #pragma unroll
            for (int c = 0; c < 4; c++) acc[i][j][c] = 0.0f;

    const int nst = K / BK;

    const int lr0 = tid >> 3;           // rows tid/8, +32, +64, +96
    const int lc  = (tid & 7) * 16;     // byte col within 128B row

    auto issue_stage = [&](int s) {
        const int buf = s & 1;
        const int k0  = s * BK;
        const uint32_t sA = sbase + buf * STAGE;
        const uint32_t sB = sA + ATILE;
        #pragma unroll
        for (int c = 0; c < 4; c++) {
            const int row = lr0 + c * 32;
            const uint32_t so = SWZ((uint32_t)(row * 128 + lc));
            const __half* gA = A + (size_t)(brow + row) * K + k0 + (lc >> 1);
            const __half* gB = B + (size_t)(bcol + row) * K + k0 + (lc >> 1);
            asm volatile("cp.async.cg.shared.global [%0], [%1], 16;"
                         :: "r"(sA + so), "l"(gA));
            asm volatile("cp.async.cg.shared.global [%0], [%1], 16;"
                         :: "r"(sB + so), "l"(gB));
        }
        asm volatile("cp.async.commit_group;" ::: "memory");
    };

    issue_stage(0);
    issue_stage(1);

    const int a_row = wm * 32 + (lane & 15);
    const int a_kb  = (lane >> 4) << 4;
    const int b_row = wn * 64 + ((lane >> 4) << 3) + (lane & 7);
    const int b_kb  = ((lane >> 3) & 1) << 4;

    for (int s = 0; s < nst; s++) {
        if (s < nst - 1) asm volatile("cp.async.wait_group 1;" ::: "memory");
        else             asm volatile("cp.async.wait_group 0;" ::: "memory");
        __syncthreads();

        const uint32_t sA = sbase + (s & 1) * STAGE;
        const uint32_t sB = sA + ATILE;

        #pragma unroll
        for (int kk = 0; kk < 4; kk++) {
            uint32_t af[2][4], bf[4][4];
            #pragma unroll
            for (int mi = 0; mi < 2; mi++)
                ldsm4(af[mi], sA + SWZ((uint32_t)((a_row + mi * 16) * 128 +
                                                  a_kb + kk * 32)));
            #pragma unroll
            for (int bj = 0; bj < 4; bj++)
                ldsm4(bf[bj], sB + SWZ((uint32_t)((b_row + bj * 16) * 128 +
                                                  b_kb + kk * 32)));
            #pragma unroll
            for (int mi = 0; mi < 2; mi++)
                #pragma unroll
                for (int ni = 0; ni < 8; ni++)
                    mma16816(acc[mi][ni], af[mi],
                             bf[ni >> 1][(ni & 1) * 2],
                             bf[ni >> 1][(ni & 1) * 2 + 1]);
        }
        __syncthreads();
        if (s + 2 < nst) issue_stage(s + 2);
    }

    const int er = brow + wm * 32 + (lane >> 2);
    const int ec = bcol + wn * 64 + (lane & 3) * 2;
    #pragma unroll
    for (int mi = 0; mi < 2; mi++) {
        #pragma unroll
        for (int half = 0; half < 2; half++) {
            const int r = er + mi * 16 + half * 8;
            #pragma unroll
            for (int ni = 0; ni < 8; ni++) {
                const int c = ec + ni * 8;
                const float d0 = acc[mi][ni][half * 2];
                const float d1 = acc[mi][ni][half * 2 + 1];
                if (EPI == EPI_HALF) {
                    *(__half2*)(Ch + (size_t)r * N + c) = __floats2half2_rn(d0, d1);
                } else if (EPI == EPI_BIAS_RES) {
                    const float2 rv = *(const float2*)(res + (size_t)r * N + c);
                    *(float2*)(Cf + (size_t)r * N + c) =
                        make_float2(d0 + bias[c] + rv.x, d1 + bias[c + 1] + rv.y);
                } else {
                    const float a = gelu_exact(d0 + bias[c]);
                    const float b = gelu_exact(d1 + bias[c + 1]);
                    *(__half2*)(Ch + (size_t)r * N + c) = __floats2half2_rn(a, b);
                }
            }
        }
    }
}

// ===========================================================================
// fp16 mma flash attention. 128 threads (4 warps), Q tile 64, KV tile 64.
// Warp w owns Q rows qt*64 + w*16 .. +15.
// ===========================================================================
__global__ void __launch_bounds__(128)
attn_mma(const __half* __restrict__ qkv, __half* __restrict__ O)
{
    __shared__ __align__(128) char qs_raw[8192];
    __shared__ __align__(128) char ks_raw[8192];
    __shared__ __align__(128) char vs_raw[8192];
    const uint32_t qs = smem_u32(qs_raw);
    const uint32_t ks = smem_u32(ks_raw);
    const uint32_t vs = smem_u32(vs_raw);

    const int qt = blockIdx.x;          // 0..15
    const int bh = blockIdx.y;          // 0..95
    const int b  = bh / NHEAD, h = bh % NHEAD;
    const int tid = threadIdx.x, lane = tid & 31, w = tid >> 5;
    const size_t rowbase = (size_t)b * TDIM;

    // load Q tile (64 rows x 64 halfs), swizzled 128B rows
    #pragma unroll
    for (int c = 0; c < 4; c++) {
        const int id = tid + c * 128;          // 0..511
        const int r = id >> 3, col = id & 7;
        const __half* src = qkv + (rowbase + qt * 64 + r) * QKVW + h * 64 + col * 8;
        *(uint4*)(qs_raw + SWZ((uint32_t)(r * 128 + col * 16))) = *(const uint4*)src;
    }
    __syncthreads();

    // Q fragments (per warp, 4 k-steps of 16)
    uint32_t qf[4][4];
    #pragma unroll
    for (int kk = 0; kk < 4; kk++)
        ldsm4(qf[kk], qs + SWZ((uint32_t)((w * 16 + (lane & 15)) * 128 +
                                          ((lane >> 4) << 4) + kk * 32)));

    float oacc[8][4];
    #pragma unroll
    for (int i = 0; i < 8; i++)
        #pragma unroll
        for (int j = 0; j < 4; j++) oacc[i][j] = 0.0f;
    float m0 = -INFINITY, m1 = -INFINITY, l0 = 0.0f, l1 = 0.0f;
    const float scale = 0.03608439182435161f;   // 768^-0.5 (C, not hs)

    const int r0 = qt * 64 + w * 16 + (lane >> 2);
    const int r1 = r0 + 8;

    for (int jt = 0; jt <= qt; jt++) {
        __syncthreads();   // ks/vs reuse safe
        #pragma unroll
        for (int c = 0; c < 4; c++) {
            const int id = tid + c * 128;
            const int r = id >> 3, col = id & 7;
            const size_t grow = (rowbase + jt * 64 + r) * QKVW + h * 64 + col * 8;
            const uint32_t so = SWZ((uint32_t)(r * 128 + col * 16));
            *(uint4*)(ks_raw + so) = *(const uint4*)(qkv + grow + 768);
            *(uint4*)(vs_raw + so) = *(const uint4*)(qkv + grow + 1536);
        }
        __syncthreads();

        // S = Q K^T   (16 x 64 per warp)
        float sacc[8][4];
        #pragma unroll
        for (int i = 0; i < 8; i++)
            #pragma unroll
            for (int j = 0; j < 4; j++) sacc[i][j] = 0.0f;
        #pragma unroll
        for (int kk = 0; kk < 4; kk++) {
            uint32_t bf[4][4];
            #pragma unroll
            for (int bj = 0; bj < 4; bj++)
                ldsm4(bf[bj], ks + SWZ((uint32_t)(
                    (((lane >> 4) << 3) + (lane & 7) + bj * 16) * 128 +
                    (((lane >> 3) & 1) << 4) + kk * 32)));
            #pragma unroll
            for (int ni = 0; ni < 8; ni++)
                mma16816(sacc[ni], qf[kk],
                         bf[ni >> 1][(ni & 1) * 2],
                         bf[ni >> 1][(ni & 1) * 2 + 1]);
        }

        // scale + causal mask (c<=r is always true for jt<qt)
        #pragma unroll
        for (int ni = 0; ni < 8; ni++) {
            const int c = jt * 64 + ni * 8 + (lane & 3) * 2;
            sacc[ni][0] = (c     <= r0) ? sacc[ni][0] * scale : -1e30f;
            sacc[ni][1] = (c + 1 <= r0) ? sacc[ni][1] * scale : -1e30f;
            sacc[ni][2] = (c     <= r1) ? sacc[ni][2] * scale : -1e30f;
            sacc[ni][3] = (c + 1 <= r1) ? sacc[ni][3] * scale : -1e30f;
        }

        // online softmax (rows r0, r1; stats across 4 lanes of the row group)
        float mx0 = -INFINITY, mx1 = -INFINITY;
        #pragma unroll
        for (int ni = 0; ni < 8; ni++) {
            mx0 = fmaxf(mx0, fmaxf(sacc[ni][0], sacc[ni][1]));
            mx1 = fmaxf(mx1, fmaxf(sacc[ni][2], sacc[ni][3]));
        }
        #pragma unroll
        for (int off = 1; off < 4; off <<= 1) {
            mx0 = fmaxf(mx0, __shfl_xor_sync(0xffffffffu, mx0, off));
            mx1 = fmaxf(mx1, __shfl_xor_sync(0xffffffffu, mx1, off));
        }
        const float m0n = fmaxf(m0, mx0), m1n = fmaxf(m1, mx1);
        const float a0 = __expf(m0 - m0n), a1 = __expf(m1 - m1n);
        m0 = m0n; m1 = m1n;

        float rs0 = 0.0f, rs1 = 0.0f;
        uint32_t pf[8][2];
        #pragma unroll
        for (int ni = 0; ni < 8; ni++) {
            const float p0 = __expf(sacc[ni][0] - m0n);
            const float p1 = __expf(sacc[ni][1] - m0n);
            const float p2 = __expf(sacc[ni][2] - m1n);
            const float p3 = __expf(sacc[ni][3] - m1n);
            rs0 += p0 + p1; rs1 += p2 + p3;
            pf[ni][0] = pack_h2(p0, p1);
            pf[ni][1] = pack_h2(p2, p3);
        }
        #pragma unroll
        for (int off = 1; off < 4; off <<= 1) {
            rs0 += __shfl_xor_sync(0xffffffffu, rs0, off);
            rs1 += __shfl_xor_sync(0xffffffffu, rs1, off);
        }
        l0 = l0 * a0 + rs0;
        l1 = l1 * a1 + rs1;
        #pragma unroll
        for (int ni = 0; ni < 8; ni++) {
            oacc[ni][0] *= a0; oacc[ni][1] *= a0;
            oacc[ni][2] *= a1; oacc[ni][3] *= a1;
        }

        // O += P V   (P as A-frags from C-frag layout; V via ldmatrix.trans)
        #pragma unroll
        for (int kk = 0; kk < 4; kk++) {
            uint32_t a[4] = { pf[2 * kk][0], pf[2 * kk][1],
                              pf[2 * kk + 1][0], pf[2 * kk + 1][1] };
            #pragma unroll
            for (int vb = 0; vb < 4; vb++) {
                uint32_t bv[4];
                ldsm4t(bv, vs + SWZ((uint32_t)(
                    (kk * 16 + ((lane >> 3) & 1) * 8 + (lane & 7)) * 128 +
                    ((lane >> 4) & 1) * 16 + vb * 32)));
                mma16816(oacc[vb * 2],     a, bv[0], bv[1]);
                mma16816(oacc[vb * 2 + 1], a, bv[2], bv[3]);
            }
        }
    }

    // epilogue
    const float il0 = 1.0f / l0, il1 = 1.0f / l1;
    const int orow = qt * 64 + w * 16 + (lane >> 2);
    #pragma unroll
    for (int ni = 0; ni < 8; ni++) {
        const int col = h * 64 + ni * 8 + (lane & 3) * 2;
        *(__half2*)(O + (rowbase + orow) * CDIM + col) =
            __floats2half2_rn(oacc[ni][0] * il0, oacc[ni][1] * il0);
        *(__half2*)(O + (rowbase + orow + 8) * CDIM + col) =
            __floats2half2_rn(oacc[ni][2] * il1, oacc[ni][3] * il1);
    }
}

// ===========================================================================
// Launch
// ===========================================================================
extern "C" void kernel_launch(void* const* d_in, const int* in_sizes, int n_in,
                              void* d_out, int out_size)
{
    const float* x   = (const float*)d_in[0];
    const float* Wq  = (const float*)d_in[1];
    const float* Wk  = (const float*)d_in[2];
    const float* Wv  = (const float*)d_in[3];
    const float* Wo  = (const float*)d_in[4];
    const float* bo  = (const float*)d_in[5];
    const float* W1  = (const float*)d_in[6];
    const float* b1  = (const float*)d_in[7];
    const float* W2  = (const float*)d_in[8];
    const float* b2  = (const float*)d_in[9];
    const float* g1  = (const float*)d_in[10];
    const float* be1 = (const float*)d_in[11];
    const float* g2  = (const float*)d_in[12];
    const float* be2 = (const float*)d_in[13];
    float* out = (float*)d_out;

    __half *h, *qkv, *att, *h2, *ff, *wqkv, *wo, *w1, *w2;
    float *x2;
    cudaGetSymbolAddress((void**)&h,    g_h);
    cudaGetSymbolAddress((void**)&qkv,  g_qkv);
    cudaGetSymbolAddress((void**)&att,  g_att);
    cudaGetSymbolAddress((void**)&h2,   g_h2);
    cudaGetSymbolAddress((void**)&ff,   g_ff);
    cudaGetSymbolAddress((void**)&wqkv, g_Wqkv);
    cudaGetSymbolAddress((void**)&wo,   g_Wo);
    cudaGetSymbolAddress((void**)&w1,   g_W1);
    cudaGetSymbolAddress((void**)&w2,   g_W2);
    cudaGetSymbolAddress((void**)&x2,   g_x2);

    cudaFuncSetAttribute(gemm_mma<EPI_HALF>,
                         cudaFuncAttributeMaxDynamicSharedMemorySize, GEMM_SMEM);
    cudaFuncSetAttribute(gemm_mma<EPI_BIAS_RES>,
                         cudaFuncAttributeMaxDynamicSharedMemorySize, GEMM_SMEM);
    cudaFuncSetAttribute(gemm_mma<EPI_BIAS_GELU_H>,
                         cudaFuncAttributeMaxDynamicSharedMemorySize, GEMM_SMEM);

    const dim3 wblk(32, 8);
    // fused QKV weight: slices of [2304, 768]
    wtrans<<<dim3(CDIM / 32, CDIM / 32), wblk>>>(Wq, wqkv,                   CDIM, CDIM);
    wtrans<<<dim3(CDIM / 32, CDIM / 32), wblk>>>(Wk, wqkv + CDIM * CDIM,     CDIM, CDIM);
    wtrans<<<dim3(CDIM / 32, CDIM / 32), wblk>>>(Wv, wqkv + 2 * CDIM * CDIM, CDIM, CDIM);
    wtrans<<<dim3(CDIM / 32, CDIM / 32), wblk>>>(Wo, wo, CDIM, CDIM);
    wtrans<<<dim3(FDIM / 32, CDIM / 32), wblk>>>(W1, w1, CDIM, FDIM);
    wtrans<<<dim3(CDIM / 32, FDIM / 32), wblk>>>(W2, w2, FDIM, CDIM);

    ln_half<<<MROWS, 192>>>(x, g1, be1, h);

    const dim3 gqkv(QKVW / 128, MROWS / 128);    // (18, 64)
    const dim3 g768(CDIM / 128, MROWS / 128);    // (6, 64)
    const dim3 g3072(FDIM / 128, MROWS / 128);   // (24, 64)

    // fused q|k|v = h @ Wqkv^T  -> fp16
    gemm_mma<EPI_HALF><<<gqkv, 256, GEMM_SMEM>>>(MROWS, QKVW, CDIM,
        h, wqkv, nullptr, nullptr, nullptr, qkv);

    attn_mma<<<dim3(TDIM / 64, BDIM * NHEAD), 128>>>(qkv, att);

    gemm_mma<EPI_BIAS_RES><<<g768, 256, GEMM_SMEM>>>(MROWS, CDIM, CDIM,
        att, wo, bo, x, x2, nullptr);

    ln_half<<<MROWS, 192>>>(x2, g2, be2, h2);

    gemm_mma<EPI_BIAS_GELU_H><<<g3072, 256, GEMM_SMEM>>>(MROWS, FDIM, CDIM,
        h2, w1, b1, nullptr, nullptr, ff);

    gemm_mma<EPI_BIAS_RES><<<g768, 256, GEMM_SMEM>>>(MROWS, CDIM, FDIM,
        ff, w2, b2, x2, out, nullptr);
}